// round 15
// baseline (speedup 1.0000x reference)
#include <cuda_runtime.h>
#include <cuda_fp16.h>
#include <cstdint>
#include <math.h>

#define BATCH 32
#define SEQ   4096
#define UNITS 1024
#define M_TOTAL (BATCH * SEQ)      // 131072
#define NBLK  8
#define KC    64
#define NCHUNK 16
#define STAGES 3
#define TILE_B 16384               // 128 rows x 128 bytes (fp16, 64 k)
#define STAGE_B (2 * TILE_B)       // Ah, Bh tiles
#define SMEM_GEMM (STAGES * STAGE_B + 2048)   // 100352
#define CTXC 16                    // ctx s-chunks

// ---------------------------------------------------------------------------
// Scratch
// ---------------------------------------------------------------------------
__device__ __half g_Ah[(size_t)M_TOTAL * UNITS];
__device__ __half g_Bh[(size_t)UNITS * UNITS];     // U_w^T [n][k] fp16
__device__ float g_ws_part[BATCH * 8 * UNITS];
__device__ float g_wsb[BATCH * UNITS];
__device__ float g_score_part[(size_t)M_TOTAL * NBLK];
__device__ float g_score[M_TOTAL];
__device__ float g_ctx_part[BATCH * CTXC * UNITS];

// ---------------------------------------------------------------------------
// PTX helpers
// ---------------------------------------------------------------------------
__device__ __forceinline__ uint32_t smem_u32(const void* p) {
    uint32_t a;
    asm("{ .reg .u64 t; cvta.to.shared.u64 t, %1; cvt.u32.u64 %0, t; }" : "=r"(a) : "l"(p));
    return a;
}
__device__ __forceinline__ void cp16(uint32_t dst, const void* src) {
    asm volatile("cp.async.cg.shared.global [%0], [%1], 16;"
                 :: "r"(dst), "l"(__cvta_generic_to_global(src)) : "memory");
}
#define CP_COMMIT() asm volatile("cp.async.commit_group;" ::: "memory")
#define CP_WAIT(n)  asm volatile("cp.async.wait_group %0;" :: "n"(n) : "memory")

__device__ __forceinline__ void ldsm4(uint32_t r[4], uint32_t addr) {
    asm volatile("ldmatrix.sync.aligned.m8n8.x4.shared.b16 {%0,%1,%2,%3}, [%4];"
                 : "=r"(r[0]), "=r"(r[1]), "=r"(r[2]), "=r"(r[3]) : "r"(addr));
}
__device__ __forceinline__ void mma_f16(float c[4], const uint32_t a[4],
                                        uint32_t b0, uint32_t b1) {
    asm volatile(
        "mma.sync.aligned.m16n8k16.row.col.f32.f16.f16.f32 "
        "{%0,%1,%2,%3}, {%4,%5,%6,%7}, {%8,%9}, {%0,%1,%2,%3};"
        : "+f"(c[0]), "+f"(c[1]), "+f"(c[2]), "+f"(c[3])
        : "r"(a[0]), "r"(a[1]), "r"(a[2]), "r"(a[3]), "r"(b0), "r"(b1));
}

// SW128 swizzle: 128x128B tile, (row, 16B-chunk c), c in 0..7
__device__ __forceinline__ uint32_t swz128(int row, int c) {
    return (uint32_t)(row * 128 + ((c ^ (row & 7)) << 4));
}

// fast tanh: 1 - 2/(exp(2x)+1)
__device__ __forceinline__ float ftanh(float x) {
    float e2 = __expf(2.f * x);
    return 1.f - __fdividef(2.f, e2 + 1.f);
}

// ---------------------------------------------------------------------------
// Prep: hidden fp32 -> fp16 (streaming hints; no L2 retention value)
// ---------------------------------------------------------------------------
__global__ void convA_kernel(const float* __restrict__ A) {
    size_t i = ((size_t)blockIdx.x * 256 + threadIdx.x) * 8;
    float4 v0 = __ldcs((const float4*)(A + i));
    float4 v1 = __ldcs((const float4*)(A + i + 4));
    __half h[8];
    float f[8] = {v0.x, v0.y, v0.z, v0.w, v1.x, v1.y, v1.z, v1.w};
    #pragma unroll
    for (int q = 0; q < 8; q++) h[q] = __float2half_rn(f[q]);
    __stcs((uint4*)(g_Ah + i), *(uint4*)h);
}

// ---------------------------------------------------------------------------
// Prep: U_w [k][n] fp32 -> transposed fp16 [n][k]
// ---------------------------------------------------------------------------
__global__ void convB_kernel(const float* __restrict__ U) {
    __shared__ float t[32][33];
    int n0 = blockIdx.x * 32, k0 = blockIdx.y * 32;
    t[threadIdx.y][threadIdx.x] = U[(size_t)(k0 + threadIdx.y) * UNITS + n0 + threadIdx.x];
    __syncthreads();
    float v = t[threadIdx.x][threadIdx.y];
    g_Bh[(size_t)(n0 + threadIdx.y) * UNITS + k0 + threadIdx.x] = __float2half_rn(v);
}

// ---------------------------------------------------------------------------
// Prep: ws partials over k-chunks of 128.  grid (BATCH, 8), block 1024.
// ---------------------------------------------------------------------------
__global__ void ws_part_kernel(const float* __restrict__ s_prev,
                               const float* __restrict__ W_w) {
    __shared__ float srow[128];
    const int b = blockIdx.x, kc = blockIdx.y, v = threadIdx.x;
    if (v < 128) srow[v] = s_prev[b * UNITS + kc * 128 + v];
    __syncthreads();
    const float* Wp = W_w + (size_t)(kc * 128) * UNITS + v;
    float a0 = 0.f, a1 = 0.f, a2 = 0.f, a3 = 0.f;
    #pragma unroll 4
    for (int k = 0; k < 128; k += 4) {
        a0 += srow[k + 0] * Wp[(size_t)(k + 0) * UNITS];
        a1 += srow[k + 1] * Wp[(size_t)(k + 1) * UNITS];
        a2 += srow[k + 2] * Wp[(size_t)(k + 2) * UNITS];
        a3 += srow[k + 3] * Wp[(size_t)(k + 3) * UNITS];
    }
    g_ws_part[(b * 8 + kc) * UNITS + v] = (a0 + a1) + (a2 + a3);
}

__global__ void ws_reduce_kernel(const float* __restrict__ W_b,
                                 const float* __restrict__ U_b) {
    const int b = blockIdx.x, v = threadIdx.x;
    float acc = W_b[v] + U_b[v];
    #pragma unroll
    for (int kc = 0; kc < 8; kc++)
        acc += g_ws_part[(b * 8 + kc) * UNITS + v];
    g_wsb[b * UNITS + v] = acc;
}

// ---------------------------------------------------------------------------
// GEMM: 128x128 CTA tile, 8 warps (4m x 2n), warp tile 32x64.
// fp16 single-term, KC=64 chunks, 3-stage cp.async, A- and B-fragment
// double buffers, fast-tanh·V epilogue.  (FROZEN — R14 best)
// grid = (NBLK, 1024), block = 256, 2 CTAs/SM.
// ---------------------------------------------------------------------------
__global__ __launch_bounds__(256, 2)
void score_gemm_mma(const float* __restrict__ V) {
    extern __shared__ char smem[];
    float* Ws = (float*)(smem + STAGES * STAGE_B);   // [128]
    float* Vs = Ws + 128;                             // [128]
    float (*sc_s)[2] = (float(*)[2])(Vs + 128);       // [128][2]

    const int nt    = blockIdx.x;
    const int mtile = blockIdx.y;
    const int tid   = threadIdx.x;
    const int lane  = tid & 31;
    const int wid   = tid >> 5;
    const int wm    = wid & 3;           // m quarter (32 rows)
    const int wn    = wid >> 2;          // n half (64 cols)
    const int b     = mtile >> 5;
    const uint32_t sbase = smem_u32(smem);

    if (tid < 128) {
        Ws[tid] = g_wsb[b * UNITS + nt * 128 + tid];
        Vs[tid] = V[nt * 128 + tid];
    }

    float acc[2][8][4];
    #pragma unroll
    for (int mi = 0; mi < 2; mi++)
        #pragma unroll
        for (int nf = 0; nf < 8; nf++)
            #pragma unroll
            for (int q = 0; q < 4; q++)
                acc[mi][nf][q] = 0.f;

    const int row0 = tid >> 3, c0 = tid & 7;
    const uint32_t cp_d0 = swz128(row0, c0);
    const __half* cpA = g_Ah + (size_t)mtile * 128 * UNITS + (size_t)row0 * UNITS + c0 * 8;
    const __half* cpB = g_Bh + (size_t)nt    * 128 * UNITS + (size_t)row0 * UNITS + c0 * 8;

    const int a_row_off = ((lane >> 3) & 1) * 8 + (lane & 7);
    const int k_sub     = lane >> 4;          // 0/1
    const int b_row_off = lane & 15;
    const int r7a = a_row_off & 7;
    const int r7b = b_row_off & 7;
    uint32_t rbA[2], rbB[4];
    #pragma unroll
    for (int mi = 0; mi < 2; mi++)
        rbA[mi] = (uint32_t)((wm * 32 + mi * 16 + a_row_off) * 128);
    #pragma unroll
    for (int p = 0; p < 4; p++)
        rbB[p] = (uint32_t)(TILE_B + (wn * 64 + p * 16 + b_row_off) * 128);

    #pragma unroll
    for (int st0 = 0; st0 < 2; st0++) {
        uint32_t sb = sbase + st0 * STAGE_B + cp_d0;
        #pragma unroll
        for (int j = 0; j < 4; j++) {
            cp16(sb + j * 4096,          cpA + j * (32 * UNITS) + st0 * KC);
            cp16(sb + TILE_B + j * 4096, cpB + j * (32 * UNITS) + st0 * KC);
        }
        CP_COMMIT();
    }

    int cons = 0, prod = 2;
    for (int kc = 0; kc < NCHUNK; kc++) {
        CP_WAIT(1);
        __syncthreads();
        if (kc + 2 < NCHUNK) {
            uint32_t sb = sbase + prod * STAGE_B + cp_d0;
            #pragma unroll
            for (int j = 0; j < 4; j++) {
                cp16(sb + j * 4096,          cpA + j * (32 * UNITS) + 2 * KC);
                cp16(sb + TILE_B + j * 4096, cpB + j * (32 * UNITS) + 2 * KC);
            }
        }
        CP_COMMIT();
        cpA += KC; cpB += KC;

        const uint32_t st = sbase + cons * STAGE_B;
        const uint32_t aAddr0 = st + rbA[0], aAddr1 = st + rbA[1];
        const uint32_t bA0 = st + rbB[0], bA1 = st + rbB[1];
        const uint32_t bA2 = st + rbB[2], bA3 = st + rbB[3];

        uint32_t a[2][2][4], bb[2][4];
        {
            const uint32_t xA0 = (uint32_t)((k_sub ^ r7a) << 4);
            ldsm4(a[0][0], aAddr0 + xA0);
            ldsm4(a[0][1], aAddr1 + xA0);
            ldsm4(bb[0], bA0 + (uint32_t)((k_sub ^ r7b) << 4));
        }
        #pragma unroll
        for (int ks = 0; ks < 4; ks++) {
            const int par = ks & 1;
            const int kk  = (ks << 1) | k_sub;
            const uint32_t xB  = (uint32_t)((kk ^ r7b) << 4);
            const uint32_t xBn = (uint32_t)(((kk + 2) ^ r7b) << 4);
            const uint32_t xAn = (uint32_t)(((kk + 2) ^ r7a) << 4);

            if (ks < 3) {
                ldsm4(a[par ^ 1][0], aAddr0 + xAn);
                ldsm4(a[par ^ 1][1], aAddr1 + xAn);
            }

            ldsm4(bb[1], bA1 + xB);
            mma_f16(acc[0][0], a[par][0], bb[0][0], bb[0][2]);
            mma_f16(acc[0][1], a[par][0], bb[0][1], bb[0][3]);
            mma_f16(acc[1][0], a[par][1], bb[0][0], bb[0][2]);
            mma_f16(acc[1][1], a[par][1], bb[0][1], bb[0][3]);
            ldsm4(bb[0], bA2 + xB);
            mma_f16(acc[0][2], a[par][0], bb[1][0], bb[1][2]);
            mma_f16(acc[0][3], a[par][0], bb[1][1], bb[1][3]);
            mma_f16(acc[1][2], a[par][1], bb[1][0], bb[1][2]);
            mma_f16(acc[1][3], a[par][1], bb[1][1], bb[1][3]);
            ldsm4(bb[1], bA3 + xB);
            mma_f16(acc[0][4], a[par][0], bb[0][0], bb[0][2]);
            mma_f16(acc[0][5], a[par][0], bb[0][1], bb[0][3]);
            mma_f16(acc[1][4], a[par][1], bb[0][0], bb[0][2]);
            mma_f16(acc[1][5], a[par][1], bb[0][1], bb[0][3]);
            if (ks < 3) ldsm4(bb[0], bA0 + xBn);
            mma_f16(acc[0][6], a[par][0], bb[1][0], bb[1][2]);
            mma_f16(acc[0][7], a[par][0], bb[1][1], bb[1][3]);
            mma_f16(acc[1][6], a[par][1], bb[1][0], bb[1][2]);
            mma_f16(acc[1][7], a[par][1], bb[1][1], bb[1][3]);
        }
        cons = (cons == 2) ? 0 : cons + 1;
        prod = (prod == 2) ? 0 : prod + 1;
    }

    const int tc = (lane & 3) * 2;
    #pragma unroll
    for (int mi = 0; mi < 2; mi++) {
        float s0 = 0.f, s1 = 0.f;
        #pragma unroll
        for (int nf = 0; nf < 8; nf++) {
            int n = wn * 64 + nf * 8 + tc;
            float w0 = Ws[n], w1 = Ws[n + 1];
            float v0 = Vs[n], v1 = Vs[n + 1];
            s0 += v0 * ftanh(w0 + acc[mi][nf][0]) + v1 * ftanh(w1 + acc[mi][nf][1]);
            s1 += v0 * ftanh(w0 + acc[mi][nf][2]) + v1 * ftanh(w1 + acc[mi][nf][3]);
        }
        s0 += __shfl_xor_sync(0xffffffffu, s0, 1);
        s0 += __shfl_xor_sync(0xffffffffu, s0, 2);
        s1 += __shfl_xor_sync(0xffffffffu, s1, 1);
        s1 += __shfl_xor_sync(0xffffffffu, s1, 2);
        if ((lane & 3) == 0) {
            int r = wm * 32 + mi * 16 + (lane >> 2);
            sc_s[r][wn]     = s0;
            sc_s[r + 8][wn] = s1;
        }
    }
    __syncthreads();
    if (tid < 128)
        g_score_part[((size_t)mtile * 128 + tid) * NBLK + nt] =
            sc_s[tid][0] + sc_s[tid][1];
}

// ---------------------------------------------------------------------------
// Score pre-sum: g_score[m] = sum of 8 partials + V_b.  512 blocks x 256.
// ---------------------------------------------------------------------------
__global__ void score_sum_kernel(const float* __restrict__ V_b) {
    const int m = blockIdx.x * 256 + threadIdx.x;
    const float4* p = (const float4*)&g_score_part[(size_t)m * NBLK];
    float4 q0 = p[0], q1 = p[1];
    g_score[m] = ((q0.x + q0.y) + (q0.z + q0.w))
               + ((q1.x + q1.y) + (q1.z + q1.w)) + V_b[0];
}

// ---------------------------------------------------------------------------
// Softmax over S per batch; writes weights.
// ---------------------------------------------------------------------------
__global__ void softmax_kernel(float* __restrict__ weights_out) {
    __shared__ float red[1024];
    const int b = blockIdx.x, t = threadIdx.x;

    float sc[4];
    float mx = -1e30f;
    #pragma unroll
    for (int j = 0; j < 4; j++) {
        sc[j] = g_score[b * SEQ + t + j * 1024];
        mx = fmaxf(mx, sc[j]);
    }
    red[t] = mx;
    __syncthreads();
    for (int o = 512; o > 0; o >>= 1) {
        if (t < o) red[t] = fmaxf(red[t], red[t + o]);
        __syncthreads();
    }
    mx = red[0];
    __syncthreads();

    float e[4], sum = 0.f;
    #pragma unroll
    for (int j = 0; j < 4; j++) { e[j] = expf(sc[j] - mx); sum += e[j]; }
    red[t] = sum;
    __syncthreads();
    for (int o = 512; o > 0; o >>= 1) {
        if (t < o) red[t] += red[t + o];
        __syncthreads();
    }
    float inv = 1.f / red[0];
    #pragma unroll
    for (int j = 0; j < 4; j++)
        weights_out[b * SEQ + t + j * 1024] = e[j] * inv;
}

// ---------------------------------------------------------------------------
// Context: weighted sum over S, fp16 g_Ah via half2.
// grid (BATCH, CTXC), block 512; s-chunks of 256.
// ---------------------------------------------------------------------------
__global__ void ctx_partial_kernel(const float* __restrict__ W) {
    const int b = blockIdx.x, cs = blockIdx.y, u2 = threadIdx.x;   // 0..511
    const float* w = W + b * SEQ + cs * 256;
    const __half2* h = (const __half2*)(g_Ah + ((size_t)b * SEQ + cs * 256) * UNITS) + u2;
    float ax = 0.f, ay = 0.f, bx = 0.f, by = 0.f;
    for (int s = 0; s < 256; s += 2) {
        float2 h0 = __half22float2(h[(size_t)(s    ) * 512]);
        float2 h1 = __half22float2(h[(size_t)(s + 1) * 512]);
        float w0 = w[s], w1 = w[s + 1];
        ax += w0 * h0.x; ay += w0 * h0.y;
        bx += w1 * h1.x; by += w1 * h1.y;
    }
    float2* out = (float2*)(g_ctx_part + (b * CTXC + cs) * UNITS) + u2;
    *out = make_float2(ax + bx, ay + by);
}

__global__ void ctx_reduce_kernel(float* __restrict__ ctx_out) {
    const int b = blockIdx.x, u = threadIdx.x;
    float acc = 0.f;
    #pragma unroll
    for (int cs = 0; cs < CTXC; cs++)
        acc += g_ctx_part[(b * CTXC + cs) * UNITS + u];
    ctx_out[b * UNITS + u] = acc;
}

// ---------------------------------------------------------------------------
extern "C" void kernel_launch(void* const* d_in, const int* in_sizes, int n_in,
                              void* d_out, int out_size) {
    const float* s_prev = (const float*)d_in[0];
    const float* hidden = (const float*)d_in[1];
    const float* W_w    = (const float*)d_in[2];
    const float* W_b    = (const float*)d_in[3];
    const float* U_w    = (const float*)d_in[4];
    const float* U_b    = (const float*)d_in[5];
    const float* V_w    = (const float*)d_in[6];
    const float* V_b    = (const float*)d_in[7];

    float* out     = (float*)d_out;
    float* ctx_out = out;                      // [32,1024]
    float* w_out   = out + BATCH * UNITS;      // [32,4096,1]

    cudaFuncSetAttribute(score_gemm_mma,
        cudaFuncAttributeMaxDynamicSharedMemorySize, SMEM_GEMM);

    convA_kernel<<<(unsigned)((size_t)M_TOTAL * UNITS / 2048), 256>>>(hidden);
    convB_kernel<<<dim3(32, 32), dim3(32, 32)>>>(U_w);
    ws_part_kernel<<<dim3(BATCH, 8), 1024>>>(s_prev, W_w);
    ws_reduce_kernel<<<BATCH, 1024>>>(W_b, U_b);
    score_gemm_mma<<<dim3(NBLK, M_TOTAL / 128), 256, SMEM_GEMM>>>(V_w);
    score_sum_kernel<<<M_TOTAL / 256, 256>>>(V_b);
    softmax_kernel<<<BATCH, 1024>>>(w_out);
    ctx_partial_kernel<<<dim3(BATCH, CTXC), 512>>>(w_out);
    ctx_reduce_kernel<<<BATCH, 1024>>>(ctx_out);
}

// round 16
// speedup vs baseline: 1.4388x; 1.4388x over previous
#include <cuda_runtime.h>
#include <cuda_fp16.h>
#include <cstdint>
#include <math.h>

#define BATCH 32
#define SEQ   4096
#define UNITS 1024
#define M_TOTAL (BATCH * SEQ)      // 131072
#define NBLK  8
#define KC    64
#define NCHUNK 16
#define STAGES 3
#define TILE_B 16384               // 128 rows x 128 bytes (fp16, 64 k)
#define STAGE_B (2 * TILE_B)       // Ah, Bh tiles
#define SMEM_GEMM (STAGES * STAGE_B + 2048)   // 100352

// ---------------------------------------------------------------------------
// Scratch
// ---------------------------------------------------------------------------
__device__ __half g_Ah[(size_t)M_TOTAL * UNITS];
__device__ __half g_Bh[(size_t)UNITS * UNITS];     // U_w^T [n][k] fp16
__device__ float g_ws_part[BATCH * 8 * UNITS];
__device__ float g_wsb[BATCH * UNITS];
__device__ float g_score_part[(size_t)M_TOTAL * NBLK];
__device__ float g_score[M_TOTAL];
__device__ float g_ctx_part[BATCH * 8 * UNITS];

// ---------------------------------------------------------------------------
// PTX helpers
// ---------------------------------------------------------------------------
__device__ __forceinline__ uint32_t smem_u32(const void* p) {
    uint32_t a;
    asm("{ .reg .u64 t; cvta.to.shared.u64 t, %1; cvt.u32.u64 %0, t; }" : "=r"(a) : "l"(p));
    return a;
}
__device__ __forceinline__ void cp16(uint32_t dst, const void* src) {
    asm volatile("cp.async.cg.shared.global [%0], [%1], 16;"
                 :: "r"(dst), "l"(__cvta_generic_to_global(src)) : "memory");
}
#define CP_COMMIT() asm volatile("cp.async.commit_group;" ::: "memory")
#define CP_WAIT(n)  asm volatile("cp.async.wait_group %0;" :: "n"(n) : "memory")

__device__ __forceinline__ void ldsm4(uint32_t r[4], uint32_t addr) {
    asm volatile("ldmatrix.sync.aligned.m8n8.x4.shared.b16 {%0,%1,%2,%3}, [%4];"
                 : "=r"(r[0]), "=r"(r[1]), "=r"(r[2]), "=r"(r[3]) : "r"(addr));
}
__device__ __forceinline__ void mma_f16(float c[4], const uint32_t a[4],
                                        uint32_t b0, uint32_t b1) {
    asm volatile(
        "mma.sync.aligned.m16n8k16.row.col.f32.f16.f16.f32 "
        "{%0,%1,%2,%3}, {%4,%5,%6,%7}, {%8,%9}, {%0,%1,%2,%3};"
        : "+f"(c[0]), "+f"(c[1]), "+f"(c[2]), "+f"(c[3])
        : "r"(a[0]), "r"(a[1]), "r"(a[2]), "r"(a[3]), "r"(b0), "r"(b1));
}

// SW128 swizzle: 128x128B tile, (row, 16B-chunk c), c in 0..7
__device__ __forceinline__ uint32_t swz128(int row, int c) {
    return (uint32_t)(row * 128 + ((c ^ (row & 7)) << 4));
}

// fast tanh: 1 - 2/(exp(2x)+1)
__device__ __forceinline__ float ftanh(float x) {
    float e2 = __expf(2.f * x);
    return 1.f - __fdividef(2.f, e2 + 1.f);
}

// ---------------------------------------------------------------------------
// Prep: hidden fp32 -> fp16 (plain loads/stores — R14 form)
// ---------------------------------------------------------------------------
__global__ void convA_kernel(const float* __restrict__ A) {
    size_t i = ((size_t)blockIdx.x * 256 + threadIdx.x) * 8;
    float4 v0 = *(const float4*)(A + i);
    float4 v1 = *(const float4*)(A + i + 4);
    __half h[8];
    float f[8] = {v0.x, v0.y, v0.z, v0.w, v1.x, v1.y, v1.z, v1.w};
    #pragma unroll
    for (int q = 0; q < 8; q++) h[q] = __float2half_rn(f[q]);
    *(uint4*)(g_Ah + i) = *(uint4*)h;
}

// ---------------------------------------------------------------------------
// Prep: U_w [k][n] fp32 -> transposed fp16 [n][k]
// ---------------------------------------------------------------------------
__global__ void convB_kernel(const float* __restrict__ U) {
    __shared__ float t[32][33];
    int n0 = blockIdx.x * 32, k0 = blockIdx.y * 32;
    t[threadIdx.y][threadIdx.x] = U[(size_t)(k0 + threadIdx.y) * UNITS + n0 + threadIdx.x];
    __syncthreads();
    float v = t[threadIdx.x][threadIdx.y];
    g_Bh[(size_t)(n0 + threadIdx.y) * UNITS + k0 + threadIdx.x] = __float2half_rn(v);
}

// ---------------------------------------------------------------------------
// Prep: ws partials over k-chunks of 128.  grid (BATCH, 8), block 1024.
// ---------------------------------------------------------------------------
__global__ void ws_part_kernel(const float* __restrict__ s_prev,
                               const float* __restrict__ W_w) {
    __shared__ float srow[128];
    const int b = blockIdx.x, kc = blockIdx.y, v = threadIdx.x;
    if (v < 128) srow[v] = s_prev[b * UNITS + kc * 128 + v];
    __syncthreads();
    const float* Wp = W_w + (size_t)(kc * 128) * UNITS + v;
    float a0 = 0.f, a1 = 0.f, a2 = 0.f, a3 = 0.f;
    #pragma unroll 4
    for (int k = 0; k < 128; k += 4) {
        a0 += srow[k + 0] * Wp[(size_t)(k + 0) * UNITS];
        a1 += srow[k + 1] * Wp[(size_t)(k + 1) * UNITS];
        a2 += srow[k + 2] * Wp[(size_t)(k + 2) * UNITS];
        a3 += srow[k + 3] * Wp[(size_t)(k + 3) * UNITS];
    }
    g_ws_part[(b * 8 + kc) * UNITS + v] = (a0 + a1) + (a2 + a3);
}

__global__ void ws_reduce_kernel(const float* __restrict__ W_b,
                                 const float* __restrict__ U_b) {
    const int b = blockIdx.x, v = threadIdx.x;
    float acc = W_b[v] + U_b[v];
    #pragma unroll
    for (int kc = 0; kc < 8; kc++)
        acc += g_ws_part[(b * 8 + kc) * UNITS + v];
    g_wsb[b * UNITS + v] = acc;
}

// ---------------------------------------------------------------------------
// GEMM: 128x128 CTA tile, 8 warps (4m x 2n), warp tile 32x64.
// fp16 single-term, KC=64 chunks, 3-stage cp.async, A- and B-fragment
// double buffers, fast-tanh·V epilogue.  (FROZEN — R14 best)
// grid = (NBLK, 1024), block = 256, 2 CTAs/SM.
// ---------------------------------------------------------------------------
__global__ __launch_bounds__(256, 2)
void score_gemm_mma(const float* __restrict__ V) {
    extern __shared__ char smem[];
    float* Ws = (float*)(smem + STAGES * STAGE_B);   // [128]
    float* Vs = Ws + 128;                             // [128]
    float (*sc_s)[2] = (float(*)[2])(Vs + 128);       // [128][2]

    const int nt    = blockIdx.x;
    const int mtile = blockIdx.y;
    const int tid   = threadIdx.x;
    const int lane  = tid & 31;
    const int wid   = tid >> 5;
    const int wm    = wid & 3;           // m quarter (32 rows)
    const int wn    = wid >> 2;          // n half (64 cols)
    const int b     = mtile >> 5;
    const uint32_t sbase = smem_u32(smem);

    if (tid < 128) {
        Ws[tid] = g_wsb[b * UNITS + nt * 128 + tid];
        Vs[tid] = V[nt * 128 + tid];
    }

    float acc[2][8][4];
    #pragma unroll
    for (int mi = 0; mi < 2; mi++)
        #pragma unroll
        for (int nf = 0; nf < 8; nf++)
            #pragma unroll
            for (int q = 0; q < 4; q++)
                acc[mi][nf][q] = 0.f;

    const int row0 = tid >> 3, c0 = tid & 7;
    const uint32_t cp_d0 = swz128(row0, c0);
    const __half* cpA = g_Ah + (size_t)mtile * 128 * UNITS + (size_t)row0 * UNITS + c0 * 8;
    const __half* cpB = g_Bh + (size_t)nt    * 128 * UNITS + (size_t)row0 * UNITS + c0 * 8;

    const int a_row_off = ((lane >> 3) & 1) * 8 + (lane & 7);
    const int k_sub     = lane >> 4;          // 0/1
    const int b_row_off = lane & 15;
    const int r7a = a_row_off & 7;
    const int r7b = b_row_off & 7;
    uint32_t rbA[2], rbB[4];
    #pragma unroll
    for (int mi = 0; mi < 2; mi++)
        rbA[mi] = (uint32_t)((wm * 32 + mi * 16 + a_row_off) * 128);
    #pragma unroll
    for (int p = 0; p < 4; p++)
        rbB[p] = (uint32_t)(TILE_B + (wn * 64 + p * 16 + b_row_off) * 128);

    #pragma unroll
    for (int st0 = 0; st0 < 2; st0++) {
        uint32_t sb = sbase + st0 * STAGE_B + cp_d0;
        #pragma unroll
        for (int j = 0; j < 4; j++) {
            cp16(sb + j * 4096,          cpA + j * (32 * UNITS) + st0 * KC);
            cp16(sb + TILE_B + j * 4096, cpB + j * (32 * UNITS) + st0 * KC);
        }
        CP_COMMIT();
    }

    int cons = 0, prod = 2;
    for (int kc = 0; kc < NCHUNK; kc++) {
        CP_WAIT(1);
        __syncthreads();
        if (kc + 2 < NCHUNK) {
            uint32_t sb = sbase + prod * STAGE_B + cp_d0;
            #pragma unroll
            for (int j = 0; j < 4; j++) {
                cp16(sb + j * 4096,          cpA + j * (32 * UNITS) + 2 * KC);
                cp16(sb + TILE_B + j * 4096, cpB + j * (32 * UNITS) + 2 * KC);
            }
        }
        CP_COMMIT();
        cpA += KC; cpB += KC;

        const uint32_t st = sbase + cons * STAGE_B;
        const uint32_t aAddr0 = st + rbA[0], aAddr1 = st + rbA[1];
        const uint32_t bA0 = st + rbB[0], bA1 = st + rbB[1];
        const uint32_t bA2 = st + rbB[2], bA3 = st + rbB[3];

        uint32_t a[2][2][4], bb[2][4];
        {
            const uint32_t xA0 = (uint32_t)((k_sub ^ r7a) << 4);
            ldsm4(a[0][0], aAddr0 + xA0);
            ldsm4(a[0][1], aAddr1 + xA0);
            ldsm4(bb[0], bA0 + (uint32_t)((k_sub ^ r7b) << 4));
        }
        #pragma unroll
        for (int ks = 0; ks < 4; ks++) {
            const int par = ks & 1;
            const int kk  = (ks << 1) | k_sub;
            const uint32_t xB  = (uint32_t)((kk ^ r7b) << 4);
            const uint32_t xBn = (uint32_t)(((kk + 2) ^ r7b) << 4);
            const uint32_t xAn = (uint32_t)(((kk + 2) ^ r7a) << 4);

            if (ks < 3) {
                ldsm4(a[par ^ 1][0], aAddr0 + xAn);
                ldsm4(a[par ^ 1][1], aAddr1 + xAn);
            }

            ldsm4(bb[1], bA1 + xB);
            mma_f16(acc[0][0], a[par][0], bb[0][0], bb[0][2]);
            mma_f16(acc[0][1], a[par][0], bb[0][1], bb[0][3]);
            mma_f16(acc[1][0], a[par][1], bb[0][0], bb[0][2]);
            mma_f16(acc[1][1], a[par][1], bb[0][1], bb[0][3]);
            ldsm4(bb[0], bA2 + xB);
            mma_f16(acc[0][2], a[par][0], bb[1][0], bb[1][2]);
            mma_f16(acc[0][3], a[par][0], bb[1][1], bb[1][3]);
            mma_f16(acc[1][2], a[par][1], bb[1][0], bb[1][2]);
            mma_f16(acc[1][3], a[par][1], bb[1][1], bb[1][3]);
            ldsm4(bb[1], bA3 + xB);
            mma_f16(acc[0][4], a[par][0], bb[0][0], bb[0][2]);
            mma_f16(acc[0][5], a[par][0], bb[0][1], bb[0][3]);
            mma_f16(acc[1][4], a[par][1], bb[0][0], bb[0][2]);
            mma_f16(acc[1][5], a[par][1], bb[0][1], bb[0][3]);
            if (ks < 3) ldsm4(bb[0], bA0 + xBn);
            mma_f16(acc[0][6], a[par][0], bb[1][0], bb[1][2]);
            mma_f16(acc[0][7], a[par][0], bb[1][1], bb[1][3]);
            mma_f16(acc[1][6], a[par][1], bb[1][0], bb[1][2]);
            mma_f16(acc[1][7], a[par][1], bb[1][1], bb[1][3]);
        }
        cons = (cons == 2) ? 0 : cons + 1;
        prod = (prod == 2) ? 0 : prod + 1;
    }

    const int tc = (lane & 3) * 2;
    #pragma unroll
    for (int mi = 0; mi < 2; mi++) {
        float s0 = 0.f, s1 = 0.f;
        #pragma unroll
        for (int nf = 0; nf < 8; nf++) {
            int n = wn * 64 + nf * 8 + tc;
            float w0 = Ws[n], w1 = Ws[n + 1];
            float v0 = Vs[n], v1 = Vs[n + 1];
            s0 += v0 * ftanh(w0 + acc[mi][nf][0]) + v1 * ftanh(w1 + acc[mi][nf][1]);
            s1 += v0 * ftanh(w0 + acc[mi][nf][2]) + v1 * ftanh(w1 + acc[mi][nf][3]);
        }
        s0 += __shfl_xor_sync(0xffffffffu, s0, 1);
        s0 += __shfl_xor_sync(0xffffffffu, s0, 2);
        s1 += __shfl_xor_sync(0xffffffffu, s1, 1);
        s1 += __shfl_xor_sync(0xffffffffu, s1, 2);
        if ((lane & 3) == 0) {
            int r = wm * 32 + mi * 16 + (lane >> 2);
            sc_s[r][wn]     = s0;
            sc_s[r + 8][wn] = s1;
        }
    }
    __syncthreads();
    if (tid < 128)
        g_score_part[((size_t)mtile * 128 + tid) * NBLK + nt] =
            sc_s[tid][0] + sc_s[tid][1];
}

// ---------------------------------------------------------------------------
// Score pre-sum: g_score[m] = sum of 8 partials + V_b.  512 blocks x 256.
// ---------------------------------------------------------------------------
__global__ void score_sum_kernel(const float* __restrict__ V_b) {
    const int m = blockIdx.x * 256 + threadIdx.x;
    const float4* p = (const float4*)&g_score_part[(size_t)m * NBLK];
    float4 q0 = p[0], q1 = p[1];
    g_score[m] = ((q0.x + q0.y) + (q0.z + q0.w))
               + ((q1.x + q1.y) + (q1.z + q1.w)) + V_b[0];
}

// ---------------------------------------------------------------------------
// Softmax over S per batch; writes weights.
// ---------------------------------------------------------------------------
__global__ void softmax_kernel(float* __restrict__ weights_out) {
    __shared__ float red[1024];
    const int b = blockIdx.x, t = threadIdx.x;

    float sc[4];
    float mx = -1e30f;
    #pragma unroll
    for (int j = 0; j < 4; j++) {
        sc[j] = g_score[b * SEQ + t + j * 1024];
        mx = fmaxf(mx, sc[j]);
    }
    red[t] = mx;
    __syncthreads();
    for (int o = 512; o > 0; o >>= 1) {
        if (t < o) red[t] = fmaxf(red[t], red[t + o]);
        __syncthreads();
    }
    mx = red[0];
    __syncthreads();

    float e[4], sum = 0.f;
    #pragma unroll
    for (int j = 0; j < 4; j++) { e[j] = expf(sc[j] - mx); sum += e[j]; }
    red[t] = sum;
    __syncthreads();
    for (int o = 512; o > 0; o >>= 1) {
        if (t < o) red[t] += red[t + o];
        __syncthreads();
    }
    float inv = 1.f / red[0];
    #pragma unroll
    for (int j = 0; j < 4; j++)
        weights_out[b * SEQ + t + j * 1024] = e[j] * inv;
}

// ---------------------------------------------------------------------------
// Context: weighted sum over S, fp16 g_Ah via half2 (R14 form).
// grid (BATCH, 8), block 512; s-chunks of 512.
// ---------------------------------------------------------------------------
__global__ void ctx_partial_kernel(const float* __restrict__ W) {
    const int b = blockIdx.x, cs = blockIdx.y, u2 = threadIdx.x;   // 0..511
    const float* w = W + b * SEQ + cs * 512;
    const __half2* h = (const __half2*)(g_Ah + ((size_t)b * SEQ + cs * 512) * UNITS) + u2;
    float ax = 0.f, ay = 0.f, bx = 0.f, by = 0.f;
    for (int s = 0; s < 512; s += 2) {
        float2 h0 = __half22float2(h[(size_t)(s    ) * 512]);
        float2 h1 = __half22float2(h[(size_t)(s + 1) * 512]);
        float w0 = w[s], w1 = w[s + 1];
        ax += w0 * h0.x; ay += w0 * h0.y;
        bx += w1 * h1.x; by += w1 * h1.y;
    }
    float2* out = (float2*)(g_ctx_part + (b * 8 + cs) * UNITS) + u2;
    *out = make_float2(ax + bx, ay + by);
}

__global__ void ctx_reduce_kernel(float* __restrict__ ctx_out) {
    const int b = blockIdx.x, u = threadIdx.x;
    float acc = 0.f;
    #pragma unroll
    for (int cs = 0; cs < 8; cs++)
        acc += g_ctx_part[(b * 8 + cs) * UNITS + u];
    ctx_out[b * UNITS + u] = acc;
}

// ---------------------------------------------------------------------------
extern "C" void kernel_launch(void* const* d_in, const int* in_sizes, int n_in,
                              void* d_out, int out_size) {
    const float* s_prev = (const float*)d_in[0];
    const float* hidden = (const float*)d_in[1];
    const float* W_w    = (const float*)d_in[2];
    const float* W_b    = (const float*)d_in[3];
    const float* U_w    = (const float*)d_in[4];
    const float* U_b    = (const float*)d_in[5];
    const float* V_w    = (const float*)d_in[6];
    const float* V_b    = (const float*)d_in[7];

    float* out     = (float*)d_out;
    float* ctx_out = out;                      // [32,1024]
    float* w_out   = out + BATCH * UNITS;      // [32,4096,1]

    cudaFuncSetAttribute(score_gemm_mma,
        cudaFuncAttributeMaxDynamicSharedMemorySize, SMEM_GEMM);

    convA_kernel<<<(unsigned)((size_t)M_TOTAL * UNITS / 2048), 256>>>(hidden);
    convB_kernel<<<dim3(32, 32), dim3(32, 32)>>>(U_w);
    ws_part_kernel<<<dim3(BATCH, 8), 1024>>>(s_prev, W_w);
    ws_reduce_kernel<<<BATCH, 1024>>>(W_b, U_b);
    score_gemm_mma<<<dim3(NBLK, M_TOTAL / 128), 256, SMEM_GEMM>>>(V_w);
    score_sum_kernel<<<M_TOTAL / 256, 256>>>(V_b);
    softmax_kernel<<<BATCH, 1024>>>(w_out);
    ctx_partial_kernel<<<dim3(BATCH, 8), 512>>>(w_out);
    ctx_reduce_kernel<<<BATCH, 1024>>>(ctx_out);
}